// round 2
// baseline (speedup 1.0000x reference)
#include <cuda_runtime.h>
#include <math.h>

// Problem dims
#define T_ 1024
#define B_ 256
#define D_ 256
#define H_ 512
#define O_ 256

// Phase A config: 128 persistent CTAs, 32x32 h-tiles (16 row-blocks x 8 col-blocks)
#define NBLK_A 128
#define WS_STRIDE 516   // padded W smem row stride (bank-shift of 4 per row)
#define SMEM_A_BYTES ((32 * WS_STRIDE + 512 * 32) * sizeof(float))

// Scratch: full hidden-state history h_t, t = 0..T-1, each (H,B) row-major. 512 MB.
__device__ float g_H[(size_t)T_ * H_ * B_];

// Grid barrier state (generation-counter barrier; safe across graph replays:
// g_gen is monotone, g_count always returns to 0 after each barrier).
__device__ unsigned int g_count = 0;
__device__ volatile unsigned int g_gen = 0;

__device__ __forceinline__ void grid_barrier() {
    __threadfence();          // make this thread's g_H stores visible device-wide
    __syncthreads();
    if (threadIdx.x == 0) {
        unsigned int my = g_gen;
        if (atomicAdd(&g_count, 1u) == NBLK_A - 1u) {
            atomicExch(&g_count, 0u);   // reset before releasing (all have arrived)
            __threadfence();
            g_gen = my + 1u;            // release
        } else {
            while (g_gen == my) { }     // spin on L2 line
        }
    }
    __syncthreads();
    __threadfence();          // acquire side
}

// ---------------------------------------------------------------------------
// Phase A: sequential recurrence. h_t = tanh(U[:,x_t] + W h_{t-1} + bh)
// Persistent kernel, one grid barrier per timestep.
// ---------------------------------------------------------------------------
__global__ void __launch_bounds__(256, 1)
rnn_recur_kernel(const int* __restrict__ inp, const float* __restrict__ h0,
                 const float* __restrict__ U, const float* __restrict__ W,
                 const float* __restrict__ bh)
{
    extern __shared__ float smem[];
    float* Ws = smem;                   // [32][WS_STRIDE]  W tile, loaded once
    float* Hs = smem + 32 * WS_STRIDE;  // [512][32]        h_{t-1} slab, per step

    const int bc = blockIdx.x & 7;      // column block (B)
    const int br = blockIdx.x >> 3;     // row block (H)
    const int r0 = br * 32, c0 = bc * 32;
    const int tid = threadIdx.x;
    const int tx = tid & 15;            // column pair -> cols 2*tx, 2*tx+1
    const int ty = tid >> 4;            // row pair    -> rows 2*ty, 2*ty+1
    const int rr = r0 + 2 * ty;
    const int cc = c0 + 2 * tx;

    // Load this block's 32x512 slab of W into smem (persists across all steps)
    for (int i = tid; i < 32 * 128; i += 256) {
        int r  = i >> 7;
        int k4 = (i & 127) << 2;
        float4 w = *(const float4*)&W[(size_t)(r0 + r) * H_ + k4];
        *(float4*)&Ws[r * WS_STRIDE + k4] = w;
    }
    const float b0 = bh[rr];
    const float b1 = bh[rr + 1];

    const float* wp0 = &Ws[(2 * ty) * WS_STRIDE];
    const float* wp1 = wp0 + WS_STRIDE;
    const float* hp  = &Hs[2 * tx];
    __syncthreads();

    for (int t = 0; t < T_; ++t) {
        // Load h_{t-1}[:, c0:c0+32] slab (written by other SMs -> bypass L1)
        const float* hsrc = (t == 0) ? h0 : (g_H + (size_t)(t - 1) * (H_ * B_));
        #pragma unroll 4
        for (int i = tid; i < 4096; i += 256) {
            int k = i >> 3;
            int j = (i & 7) << 2;
            float4 v = __ldcg((const float4*)&hsrc[(size_t)k * B_ + c0 + j]);
            *(float4*)&Hs[k * 32 + j] = v;
        }
        __syncthreads();

        // Accumulator init: U column-gather + bias
        const int x0 = inp[t * B_ + cc];
        const int x1 = inp[t * B_ + cc + 1];
        float a00 = U[(size_t)rr * D_ + x0] + b0;
        float a01 = U[(size_t)rr * D_ + x1] + b0;
        float a10 = U[(size_t)(rr + 1) * D_ + x0] + b1;
        float a11 = U[(size_t)(rr + 1) * D_ + x1] + b1;

        // 2x2 micro-tile GEMV over K = 512 (FFMA-pipe bound)
        #pragma unroll 8
        for (int k = 0; k < H_; ++k) {
            float2 h2 = *(const float2*)&hp[k * 32];
            float  w0 = wp0[k];
            float  w1 = wp1[k];
            a00 = fmaf(w0, h2.x, a00);
            a01 = fmaf(w0, h2.y, a01);
            a10 = fmaf(w1, h2.x, a10);
            a11 = fmaf(w1, h2.y, a11);
        }

        float* dst = g_H + (size_t)t * (H_ * B_);
        float2 o0 = make_float2(tanhf(a00), tanhf(a01));
        float2 o1 = make_float2(tanhf(a10), tanhf(a11));
        *(float2*)&dst[(size_t)rr * B_ + cc]       = o0;
        *(float2*)&dst[(size_t)(rr + 1) * B_ + cc] = o1;

        grid_barrier();
    }
}

// ---------------------------------------------------------------------------
// Phase B: logits[t, b, o] = by[o] + sum_h V[o,h] * g_H[t, h, b]
// Tiled GEMM: per block a (t, 32b, 64o) tile, K = 512 in chunks of 32.
// ---------------------------------------------------------------------------
__global__ void __launch_bounds__(256, 2)
rnn_logits_kernel(const float* __restrict__ Vm, const float* __restrict__ by,
                  float* __restrict__ out)
{
    __shared__ float As[32][32];   // [k][b]
    __shared__ float Vs[32][68];   // [k][o], padded

    const int t  = blockIdx.z;
    const int ob = blockIdx.x * 64;
    const int bb = blockIdx.y * 32;
    const int tid = threadIdx.x;
    const int tx = tid & 15;   // o quad -> 4*tx
    const int ty = tid >> 4;   // b pair -> 2*ty

    const float* A = g_H + (size_t)t * (H_ * B_) + bb;

    float acc00 = 0.f, acc01 = 0.f, acc02 = 0.f, acc03 = 0.f;
    float acc10 = 0.f, acc11 = 0.f, acc12 = 0.f, acc13 = 0.f;

    for (int kc = 0; kc < H_; kc += 32) {
        // A tile: 32k x 32b = 256 float4 (one per thread)
        {
            int k = tid >> 3;
            int j = (tid & 7) << 2;
            *(float4*)&As[k][j] =
                *(const float4*)&A[(size_t)(kc + k) * B_ + j];
        }
        // V tile: 64o x 32k, transposed into [k][o]
        #pragma unroll
        for (int i = tid; i < 512; i += 256) {
            int o = i >> 3;
            int j = (i & 7) << 2;
            float4 v = *(const float4*)&Vm[(size_t)(ob + o) * H_ + kc + j];
            Vs[j + 0][o] = v.x;
            Vs[j + 1][o] = v.y;
            Vs[j + 2][o] = v.z;
            Vs[j + 3][o] = v.w;
        }
        __syncthreads();

        #pragma unroll
        for (int k = 0; k < 32; ++k) {
            float2 a2 = *(const float2*)&As[k][2 * ty];
            float4 v4 = *(const float4*)&Vs[k][4 * tx];
            acc00 = fmaf(a2.x, v4.x, acc00);
            acc01 = fmaf(a2.x, v4.y, acc01);
            acc02 = fmaf(a2.x, v4.z, acc02);
            acc03 = fmaf(a2.x, v4.w, acc03);
            acc10 = fmaf(a2.y, v4.x, acc10);
            acc11 = fmaf(a2.y, v4.y, acc11);
            acc12 = fmaf(a2.y, v4.z, acc12);
            acc13 = fmaf(a2.y, v4.w, acc13);
        }
        __syncthreads();
    }

    const float4 byv = *(const float4*)&by[ob + 4 * tx];
    float4 r0 = make_float4(acc00 + byv.x, acc01 + byv.y,
                            acc02 + byv.z, acc03 + byv.w);
    float4 r1 = make_float4(acc10 + byv.x, acc11 + byv.y,
                            acc12 + byv.z, acc13 + byv.w);
    const size_t base = (size_t)t * (B_ * O_);
    *(float4*)&out[base + (size_t)(bb + 2 * ty)     * O_ + ob + 4 * tx] = r0;
    *(float4*)&out[base + (size_t)(bb + 2 * ty + 1) * O_ + ob + 4 * tx] = r1;
}

// Optional: append hT = h_{T-1} (H,B) after the logits, if the output expects it.
__global__ void copy_hT_kernel(float* __restrict__ out) {
    int i = blockIdx.x * 256 + threadIdx.x;
    out[i] = g_H[(size_t)(T_ - 1) * (H_ * B_) + i];
}

extern "C" void kernel_launch(void* const* d_in, const int* in_sizes, int n_in,
                              void* d_out, int out_size) {
    const int*   inp = (const int*)d_in[0];
    const float* h0  = (const float*)d_in[1];
    const float* U   = (const float*)d_in[2];
    const float* W   = (const float*)d_in[3];
    const float* Vm  = (const float*)d_in[4];
    const float* bh  = (const float*)d_in[5];
    const float* by  = (const float*)d_in[6];
    float* out = (float*)d_out;

    cudaFuncSetAttribute(rnn_recur_kernel,
                         cudaFuncAttributeMaxDynamicSharedMemorySize,
                         (int)SMEM_A_BYTES);

    // Phase A: persistent recurrence (one launch, internal grid barrier per step)
    rnn_recur_kernel<<<NBLK_A, 256, SMEM_A_BYTES>>>(inp, h0, U, W, bh);

    // Phase B: batched logits GEMM over all timesteps
    dim3 gridB(O_ / 64, B_ / 32, T_);
    rnn_logits_kernel<<<gridB, 256>>>(Vm, by, out);

    // If harness output also contains hT (H*B fp32 appended after logits)
    if (out_size >= T_ * B_ * O_ + H_ * B_) {
        copy_hT_kernel<<<(H_ * B_) / 256, 256>>>(out + (size_t)T_ * B_ * O_);
    }
}

// round 3
// speedup vs baseline: 1.1263x; 1.1263x over previous
#include <cuda_runtime.h>
#include <math.h>
#include <stdint.h>

// Problem dims
#define T_ 1024
#define B_ 256
#define D_ 256
#define H_ 512
#define O_ 256

// Phase A: 128 persistent CTAs, 32(h)x32(b) tiles: 16 row-blocks x 8 col-blocks
#define NBLK_A 128
#define NGRP 8            // barrier tree: 8 groups x 16 blocks

// Hidden-state history, stored (T, B, H) — h contiguous (k-major for both phases)
__device__ float g_H[(size_t)T_ * B_ * H_];
__device__ float g_h0t[B_ * H_];      // h0 transposed to (B, H)
__device__ float g_Vt[H_ * O_];       // V transposed to (H, O)

// Tree barrier state (monotone generation counter -> graph-replay safe)
__device__ unsigned int g_cnt[NGRP];
__device__ unsigned int g_root;
__device__ volatile unsigned int g_gen;

__device__ __forceinline__ unsigned smem_u32(const void* p) {
    return (unsigned)__cvta_generic_to_shared(p);
}
__device__ __forceinline__ void cp16(unsigned dst, const void* src) {
    asm volatile("cp.async.cg.shared.global [%0], [%1], 16;\n" ::"r"(dst), "l"(src));
}
__device__ __forceinline__ void cp_commit() {
    asm volatile("cp.async.commit_group;\n");
}
template <int N> __device__ __forceinline__ void cp_wait() {
    asm volatile("cp.async.wait_group %0;\n" ::"n"(N));
}

__device__ __forceinline__ void grid_barrier(int bid) {
    __threadfence();          // release: make this thread's h stores visible
    __syncthreads();
    if (threadIdx.x == 0) {
        unsigned my = g_gen;
        if (atomicAdd(&g_cnt[bid & (NGRP - 1)], 1u) == (NBLK_A / NGRP - 1u)) {
            if (atomicAdd(&g_root, 1u) == NGRP - 1u) {
                // all arrived: reset counters, then release
                atomicExch(&g_root, 0u);
                #pragma unroll
                for (int i = 0; i < NGRP; ++i) atomicExch(&g_cnt[i], 0u);
                __threadfence();
                g_gen = my + 1u;
            }
        }
        while (g_gen == my) { }
    }
    __syncthreads();
    __threadfence();          // acquire
}

// ---------------------------------------------------------------------------
// Prep: transpose h0 (H,B)->(B,H) and V (O,H)->(H,O). Tiny, runs once per replay.
// ---------------------------------------------------------------------------
__global__ void prep_h0t(const float* __restrict__ h0) {
    int b = blockIdx.x;               // 256 blocks
    int h = threadIdx.x;              // 512 threads
    g_h0t[(size_t)b * H_ + h] = h0[(size_t)h * B_ + b];
}
__global__ void prep_vt(const float* __restrict__ V) {
    int h = blockIdx.x;               // 512 blocks
    int o = threadIdx.x;              // 256 threads
    g_Vt[(size_t)h * O_ + o] = V[(size_t)o * H_ + h];
}

// ---------------------------------------------------------------------------
// Phase A: h_t = tanh(U[:,x_t] + W h_{t-1} + bh), persistent + grid barrier.
// Ws: swizzled [32 rows][512 k], Hs: [32 cols][516 k]. Micro-tile 2h x 2b.
// ---------------------------------------------------------------------------
#define SMEM_A_WORDS (32 * 512 + 32 * 516)
__global__ void __launch_bounds__(256, 1)
rnn_recur_kernel(const int* __restrict__ inp, const float* __restrict__ U,
                 const float* __restrict__ W, const float* __restrict__ bh)
{
    extern __shared__ float smem[];
    float* Ws = smem;                  // 32*512 words, XOR-swizzled 16B chunks
    float* Hs = smem + 32 * 512;       // 32*516 words, Hs[col][k]

    const int bid = blockIdx.x;
    const int br = bid >> 3, bc = bid & 7;
    const int r0 = br * 32, c0 = bc * 32;
    const int tid = threadIdx.x;
    const int tx = tid & 15;           // h-row pair: rows 2tx, 2tx+1
    const int ty = tid >> 4;           // b-col pair: cols 2ty, 2ty+1
    const int row  = r0 + 2 * tx;
    const int colb = c0 + 2 * ty;

    // Load W slab (32 rows x 512 k) once, swizzled: word = r*512 + (k4 ^ (((r>>1)&7)<<2))
    for (int i = tid; i < 4096; i += 256) {
        int r  = i >> 7;
        int k4 = (i & 127) << 2;
        float4 w = *(const float4*)&W[(size_t)(r0 + r) * H_ + k4];
        int o = k4 ^ (((r >> 1) & 7) << 2);
        *(float4*)&Ws[r * 512 + o] = w;
    }
    const float b0 = bh[row];
    const float b1 = bh[row + 1];

    const float* w0p = Ws + (2 * tx) * 512;
    const float* w1p = w0p + 512;
    const int    sx  = (tx & 7) << 2;          // same swizzle for rows 2tx, 2tx+1
    const float* h0p = Hs + (2 * ty) * 516;
    const float* h1p = h0p + 516;
    const unsigned sbase = smem_u32(Hs);

    __syncthreads();

    const float* hprev = g_h0t;                // (B, H)
    float*       hdst  = g_H;

    for (int t = 0; t < T_; ++t) {
        // Async slab load: Hs[col][k] = hprev[(c0+col)*H + k], split in k-halves
        #pragma unroll
        for (int j = 0; j < 8; ++j) {          // half 1: k in [0,256)
            int i   = tid + j * 256;           // 0..2047
            int col = i >> 6;
            int k4  = (i & 63) << 2;
            cp16(sbase + (unsigned)((col * 516 + k4) << 2),
                 hprev + (size_t)(c0 + col) * H_ + k4);
        }
        cp_commit();
        #pragma unroll
        for (int j = 0; j < 8; ++j) {          // half 2: k in [256,512)
            int i   = tid + j * 256;
            int col = i >> 6;
            int k4  = ((i & 63) << 2) + 256;
            cp16(sbase + (unsigned)((col * 516 + k4) << 2),
                 hprev + (size_t)(c0 + col) * H_ + k4);
        }
        cp_commit();

        // U column-gather + bias (overlaps cp.async)
        const int x0 = inp[t * B_ + colb];
        const int x1 = inp[t * B_ + colb + 1];
        float a00 = U[(size_t)row * D_ + x0] + b0;          // (row,   colb)
        float a01 = U[(size_t)row * D_ + x1] + b0;          // (row,   colb+1)
        float a10 = U[(size_t)(row + 1) * D_ + x0] + b1;    // (row+1, colb)
        float a11 = U[(size_t)(row + 1) * D_ + x1] + b1;

        cp_wait<1>();
        __syncthreads();
        #pragma unroll 4
        for (int k4 = 0; k4 < 256; k4 += 4) {
            int o = k4 ^ sx;
            float4 Wa = *(const float4*)(w0p + o);
            float4 Wb = *(const float4*)(w1p + o);
            float4 Ha = *(const float4*)(h0p + k4);
            float4 Hb = *(const float4*)(h1p + k4);
            a00 = fmaf(Wa.x, Ha.x, a00); a01 = fmaf(Wa.x, Hb.x, a01);
            a10 = fmaf(Wb.x, Ha.x, a10); a11 = fmaf(Wb.x, Hb.x, a11);
            a00 = fmaf(Wa.y, Ha.y, a00); a01 = fmaf(Wa.y, Hb.y, a01);
            a10 = fmaf(Wb.y, Ha.y, a10); a11 = fmaf(Wb.y, Hb.y, a11);
            a00 = fmaf(Wa.z, Ha.z, a00); a01 = fmaf(Wa.z, Hb.z, a01);
            a10 = fmaf(Wb.z, Ha.z, a10); a11 = fmaf(Wb.z, Hb.z, a11);
            a00 = fmaf(Wa.w, Ha.w, a00); a01 = fmaf(Wa.w, Hb.w, a01);
            a10 = fmaf(Wb.w, Ha.w, a10); a11 = fmaf(Wb.w, Hb.w, a11);
        }
        cp_wait<0>();
        __syncthreads();
        #pragma unroll 4
        for (int k4 = 256; k4 < 512; k4 += 4) {
            int o = k4 ^ sx;
            float4 Wa = *(const float4*)(w0p + o);
            float4 Wb = *(const float4*)(w1p + o);
            float4 Ha = *(const float4*)(h0p + k4);
            float4 Hb = *(const float4*)(h1p + k4);
            a00 = fmaf(Wa.x, Ha.x, a00); a01 = fmaf(Wa.x, Hb.x, a01);
            a10 = fmaf(Wb.x, Ha.x, a10); a11 = fmaf(Wb.x, Hb.x, a11);
            a00 = fmaf(Wa.y, Ha.y, a00); a01 = fmaf(Wa.y, Hb.y, a01);
            a10 = fmaf(Wb.y, Ha.y, a10); a11 = fmaf(Wb.y, Hb.y, a11);
            a00 = fmaf(Wa.z, Ha.z, a00); a01 = fmaf(Wa.z, Hb.z, a01);
            a10 = fmaf(Wb.z, Ha.z, a10); a11 = fmaf(Wb.z, Hb.z, a11);
            a00 = fmaf(Wa.w, Ha.w, a00); a01 = fmaf(Wa.w, Hb.w, a01);
            a10 = fmaf(Wb.w, Ha.w, a10); a11 = fmaf(Wb.w, Hb.w, a11);
        }

        // Store h_t tile, (B,H): coalesced STG.64 across tx lanes
        *(float2*)&hdst[(size_t)colb * H_ + row] =
            make_float2(tanhf(a00), tanhf(a10));
        *(float2*)&hdst[(size_t)(colb + 1) * H_ + row] =
            make_float2(tanhf(a01), tanhf(a11));

        hprev = hdst;
        hdst += (size_t)B_ * H_;
        grid_barrier(bid);
    }
}

// ---------------------------------------------------------------------------
// Phase B: out[t,b,o] = by[o] + sum_k g_H[t,b,k] * Vt[k,o]
// Tile 64b x 128o per CTA, K-chunks of 32. Micro-tile 4b x (4+4)o per thread.
// ---------------------------------------------------------------------------
__global__ void __launch_bounds__(256)
rnn_logits_kernel(const float* __restrict__ by, float* __restrict__ out)
{
    __shared__ float As[32][68];     // [k][b]
    __shared__ float Vs[32][132];    // [k][o]

    const int t  = blockIdx.z;
    const int ob = blockIdx.x * 128;
    const int bb = blockIdx.y * 64;
    const int tid = threadIdx.x;
    const int tx = tid & 15;         // o quads: 4tx and 64+4tx
    const int ty = tid >> 4;         // b quad:  4ty..4ty+3

    const float* A = g_H + (size_t)t * (B_ * H_) + (size_t)bb * H_;

    float acc[4][8];
    #pragma unroll
    for (int m = 0; m < 4; ++m)
        #pragma unroll
        for (int n = 0; n < 8; ++n) acc[m][n] = 0.f;

    for (int kc = 0; kc < H_; kc += 32) {
        // A chunk: 64b x 32k (k-contiguous) -> transpose-store into As[k][b]
        #pragma unroll
        for (int j = 0; j < 2; ++j) {
            int i  = tid + j * 256;
            int b  = i >> 3;
            int k4 = (i & 7) << 2;
            float4 v = *(const float4*)&A[(size_t)b * H_ + kc + k4];
            As[k4 + 0][b] = v.x; As[k4 + 1][b] = v.y;
            As[k4 + 2][b] = v.z; As[k4 + 3][b] = v.w;
        }
        // Vt chunk: 32k x 128o, already o-contiguous -> direct STS.128
        #pragma unroll
        for (int j = 0; j < 4; ++j) {
            int i  = tid + j * 256;
            int k  = i >> 5;
            int o4 = (i & 31) << 2;
            *(float4*)&Vs[k][o4] =
                *(const float4*)&g_Vt[(size_t)(kc + k) * O_ + ob + o4];
        }
        __syncthreads();

        #pragma unroll
        for (int k = 0; k < 32; ++k) {
            float4 a4 = *(const float4*)&As[k][4 * ty];
            float4 va = *(const float4*)&Vs[k][4 * tx];
            float4 vb = *(const float4*)&Vs[k][64 + 4 * tx];
            acc[0][0] = fmaf(a4.x, va.x, acc[0][0]);
            acc[0][1] = fmaf(a4.x, va.y, acc[0][1]);
            acc[0][2] = fmaf(a4.x, va.z, acc[0][2]);
            acc[0][3] = fmaf(a4.x, va.w, acc[0][3]);
            acc[0][4] = fmaf(a4.x, vb.x, acc[0][4]);
            acc[0][5] = fmaf(a4.x, vb.y, acc[0][5]);
            acc[0][6] = fmaf(a4.x, vb.z, acc[0][6]);
            acc[0][7] = fmaf(a4.x, vb.w, acc[0][7]);
            acc[1][0] = fmaf(a4.y, va.x, acc[1][0]);
            acc[1][1] = fmaf(a4.y, va.y, acc[1][1]);
            acc[1][2] = fmaf(a4.y, va.z, acc[1][2]);
            acc[1][3] = fmaf(a4.y, va.w, acc[1][3]);
            acc[1][4] = fmaf(a4.y, vb.x, acc[1][4]);
            acc[1][5] = fmaf(a4.y, vb.y, acc[1][5]);
            acc[1][6] = fmaf(a4.y, vb.z, acc[1][6]);
            acc[1][7] = fmaf(a4.y, vb.w, acc[1][7]);
            acc[2][0] = fmaf(a4.z, va.x, acc[2][0]);
            acc[2][1] = fmaf(a4.z, va.y, acc[2][1]);
            acc[2][2] = fmaf(a4.z, va.z, acc[2][2]);
            acc[2][3] = fmaf(a4.z, va.w, acc[2][3]);
            acc[2][4] = fmaf(a4.z, vb.x, acc[2][4]);
            acc[2][5] = fmaf(a4.z, vb.y, acc[2][5]);
            acc[2][6] = fmaf(a4.z, vb.z, acc[2][6]);
            acc[2][7] = fmaf(a4.z, vb.w, acc[2][7]);
            acc[3][0] = fmaf(a4.w, va.x, acc[3][0]);
            acc[3][1] = fmaf(a4.w, va.y, acc[3][1]);
            acc[3][2] = fmaf(a4.w, va.z, acc[3][2]);
            acc[3][3] = fmaf(a4.w, va.w, acc[3][3]);
            acc[3][4] = fmaf(a4.w, vb.x, acc[3][4]);
            acc[3][5] = fmaf(a4.w, vb.y, acc[3][5]);
            acc[3][6] = fmaf(a4.w, vb.z, acc[3][6]);
            acc[3][7] = fmaf(a4.w, vb.w, acc[3][7]);
        }
        __syncthreads();
    }

    const float4 bya = *(const float4*)&by[ob + 4 * tx];
    const float4 byb = *(const float4*)&by[ob + 64 + 4 * tx];
    #pragma unroll
    for (int m = 0; m < 4; ++m) {
        size_t base = ((size_t)t * B_ + bb + 4 * ty + m) * O_ + ob;
        float4 r1 = make_float4(acc[m][0] + bya.x, acc[m][1] + bya.y,
                                acc[m][2] + bya.z, acc[m][3] + bya.w);
        float4 r2 = make_float4(acc[m][4] + byb.x, acc[m][5] + byb.y,
                                acc[m][6] + byb.z, acc[m][7] + byb.w);
        *(float4*)&out[base + 4 * tx]      = r1;
        *(float4*)&out[base + 64 + 4 * tx] = r2;
    }
}

// Optional hT (H,B) appended after logits
__global__ void copy_hT_kernel(float* __restrict__ out) {
    int h = blockIdx.x;      // 512
    int b = threadIdx.x;     // 256
    out[(size_t)h * B_ + b] =
        g_H[(size_t)(T_ - 1) * (B_ * H_) + (size_t)b * H_ + h];
}

extern "C" void kernel_launch(void* const* d_in, const int* in_sizes, int n_in,
                              void* d_out, int out_size) {
    const int*   inp = (const int*)d_in[0];
    const float* h0  = (const float*)d_in[1];
    const float* U   = (const float*)d_in[2];
    const float* W   = (const float*)d_in[3];
    const float* Vm  = (const float*)d_in[4];
    const float* bh  = (const float*)d_in[5];
    const float* by  = (const float*)d_in[6];
    float* out = (float*)d_out;

    cudaFuncSetAttribute(rnn_recur_kernel,
                         cudaFuncAttributeMaxDynamicSharedMemorySize,
                         (int)(SMEM_A_WORDS * sizeof(float)));

    prep_h0t<<<B_, H_>>>(h0);
    prep_vt<<<H_, O_>>>(Vm);

    rnn_recur_kernel<<<NBLK_A, 256, SMEM_A_WORDS * sizeof(float)>>>(inp, U, W, bh);

    dim3 gridB(O_ / 128, B_ / 64, T_);
    rnn_logits_kernel<<<gridB, 256>>>(by, out);

    if (out_size >= T_ * B_ * O_ + H_ * B_) {
        copy_hT_kernel<<<H_, B_>>>(out + (size_t)T_ * B_ * O_);
    }
}

// round 4
// speedup vs baseline: 1.2662x; 1.1242x over previous
#include <cuda_runtime.h>
#include <math.h>
#include <stdint.h>

// Problem dims
#define T_ 1024
#define B_ 256
#define D_ 256
#define H_ 512
#define O_ 256

#define NBLK_A 128
#define NGRP 8

typedef unsigned long long ull;

// Hidden-state history (T, B, H) — h contiguous
__device__ float g_H[(size_t)T_ * B_ * H_];
__device__ float g_h0t[B_ * H_];      // h0 transposed to (B, H)

// Tree barrier (monotone generation -> graph-replay safe)
__device__ unsigned g_cnt[NGRP];
__device__ unsigned g_root;
__device__ volatile unsigned g_gen;

// ---- packed fp32 FMA: d.lo += a.lo*b.lo ; d.hi += a.hi*b.hi (exact fp32) ----
__device__ __forceinline__ void fma2(ull& d, ull a, ull b) {
    asm("fma.rn.f32x2 %0, %1, %2, %0;" : "+l"(d) : "l"(a), "l"(b));
}
__device__ __forceinline__ float pair_sum(ull v) {
    return __uint_as_float((unsigned)(v & 0xffffffffull)) +
           __uint_as_float((unsigned)(v >> 32));
}

__device__ __forceinline__ unsigned smem_u32(const void* p) {
    return (unsigned)__cvta_generic_to_shared(p);
}
__device__ __forceinline__ void cp16(unsigned dst, const void* src) {
    asm volatile("cp.async.cg.shared.global [%0], [%1], 16;\n" ::"r"(dst), "l"(src));
}
__device__ __forceinline__ void cp_commit() {
    asm volatile("cp.async.commit_group;\n");
}
template <int N> __device__ __forceinline__ void cp_wait() {
    asm volatile("cp.async.wait_group %0;\n" ::"n"(N));
}

__device__ __forceinline__ void grid_barrier(int bid) {
    __threadfence();
    __syncthreads();
    if (threadIdx.x == 0) {
        unsigned my = g_gen;
        if (atomicAdd(&g_cnt[bid & (NGRP - 1)], 1u) == (NBLK_A / NGRP - 1u)) {
            if (atomicAdd(&g_root, 1u) == NGRP - 1u) {
                atomicExch(&g_root, 0u);
                #pragma unroll
                for (int i = 0; i < NGRP; ++i) atomicExch(&g_cnt[i], 0u);
                __threadfence();
                g_gen = my + 1u;
            }
        }
        while (g_gen == my) { }
    }
    __syncthreads();
    __threadfence();
}

// Prep: h0 (H,B) -> (B,H)
__global__ void prep_h0t(const float* __restrict__ h0) {
    int b = blockIdx.x;               // 256
    int h = threadIdx.x;              // 512
    g_h0t[(size_t)b * H_ + h] = h0[(size_t)h * B_ + b];
}

// ---------------------------------------------------------------------------
// Phase A: h_t = tanh(U[:,x_t] + W h_{t-1} + bh). 128 CTAs x 128 threads.
// Tile 32h x 32b; thread = 2h x 4b; k-split f32x2 accumulators.
// Ws[32][512] XOR-swizzled; Hs[32][516] (k contiguous).
// ---------------------------------------------------------------------------
#define HS_STRIDE 516
#define SMEM_A_WORDS (32 * 512 + 32 * HS_STRIDE)

__global__ void __launch_bounds__(128, 1)
rnn_recur_kernel(const int* __restrict__ inp, const float* __restrict__ U,
                 const float* __restrict__ W, const float* __restrict__ bh)
{
    extern __shared__ float smem[];
    float* Ws = smem;                   // 32*512
    float* Hs = smem + 32 * 512;        // 32*516

    const int bid = blockIdx.x;
    const int br = bid >> 3, bc = bid & 7;
    const int r0 = br * 32, c0 = bc * 32;
    const int tid = threadIdx.x;
    const int tx = tid & 15;            // rows 2tx, 2tx+1
    const int ty = tid >> 4;            // cols 4ty .. 4ty+3
    const int row  = r0 + 2 * tx;
    const int colb = c0 + 4 * ty;

    // Load W slab (32 x 512) once, 16B-chunk XOR swizzle per row-pair
    for (int i = tid; i < 4096; i += 128) {
        int r  = i >> 7;
        int k4 = (i & 127) << 2;
        float4 w = *(const float4*)&W[(size_t)(r0 + r) * H_ + k4];
        int o = k4 ^ (((r >> 1) & 7) << 2);
        *(float4*)&Ws[r * 512 + o] = w;
    }
    const float b0 = bh[row];
    const float b1 = bh[row + 1];

    const float* w0p = Ws + (2 * tx) * 512;
    const float* w1p = w0p + 512;
    const int    sx  = (tx & 7) << 2;
    const float* hp  = Hs + (4 * ty) * HS_STRIDE;
    const unsigned sbase = smem_u32(Hs);

    __syncthreads();

    const float* hprev = g_h0t;
    float*       hdst  = g_H;

    for (int t = 0; t < T_; ++t) {
        // Async slab fill (64 KB), two k-halves for load/compute overlap
        #pragma unroll
        for (int j = 0; j < 16; ++j) {
            int i   = tid + j * 128;          // 0..2047
            int col = i >> 6;
            int k4  = (i & 63) << 2;          // k in [0,256)
            cp16(sbase + (unsigned)((col * HS_STRIDE + k4) << 2),
                 hprev + (size_t)(c0 + col) * H_ + k4);
        }
        cp_commit();
        #pragma unroll
        for (int j = 0; j < 16; ++j) {
            int i   = tid + j * 128;
            int col = i >> 6;
            int k4  = ((i & 63) << 2) + 256;  // k in [256,512)
            cp16(sbase + (unsigned)((col * HS_STRIDE + k4) << 2),
                 hprev + (size_t)(c0 + col) * H_ + k4);
        }
        cp_commit();

        // U column-gather + bias (overlaps cp.async)
        int xs[4];
        #pragma unroll
        for (int c = 0; c < 4; ++c) xs[c] = inp[t * B_ + colb + c];
        float u0[4], u1[4];
        #pragma unroll
        for (int c = 0; c < 4; ++c) {
            u0[c] = U[(size_t)row * D_ + xs[c]];
            u1[c] = U[(size_t)(row + 1) * D_ + xs[c]];
        }

        ull a0[4] = {0, 0, 0, 0};   // row 2tx,   cols c: (even-k, odd-k) partials
        ull a1[4] = {0, 0, 0, 0};   // row 2tx+1

        cp_wait<1>();
        __syncthreads();
        #pragma unroll 4
        for (int k4 = 0; k4 < 256; k4 += 4) {
            int o = k4 ^ sx;
            ulonglong2 wa = *(const ulonglong2*)(w0p + o);
            ulonglong2 wb = *(const ulonglong2*)(w1p + o);
            #pragma unroll
            for (int c = 0; c < 4; ++c) {
                ulonglong2 hc = *(const ulonglong2*)(hp + c * HS_STRIDE + k4);
                fma2(a0[c], wa.x, hc.x);
                fma2(a1[c], wb.x, hc.x);
                fma2(a0[c], wa.y, hc.y);
                fma2(a1[c], wb.y, hc.y);
            }
        }
        cp_wait<0>();
        __syncthreads();
        #pragma unroll 4
        for (int k4 = 256; k4 < 512; k4 += 4) {
            int o = k4 ^ sx;
            ulonglong2 wa = *(const ulonglong2*)(w0p + o);
            ulonglong2 wb = *(const ulonglong2*)(w1p + o);
            #pragma unroll
            for (int c = 0; c < 4; ++c) {
                ulonglong2 hc = *(const ulonglong2*)(hp + c * HS_STRIDE + k4);
                fma2(a0[c], wa.x, hc.x);
                fma2(a1[c], wb.x, hc.x);
                fma2(a0[c], wa.y, hc.y);
                fma2(a1[c], wb.y, hc.y);
            }
        }

        // Combine partials, tanh, store to (B,H)
        #pragma unroll
        for (int c = 0; c < 4; ++c) {
            float h0v = tanhf(pair_sum(a0[c]) + u0[c] + b0);
            float h1v = tanhf(pair_sum(a1[c]) + u1[c] + b1);
            *(float2*)&hdst[(size_t)(colb + c) * H_ + row] =
                make_float2(h0v, h1v);
        }

        hprev = hdst;
        hdst += (size_t)B_ * H_;
        grid_barrier(bid);
    }
}

// ---------------------------------------------------------------------------
// Phase B: out[t,b,o] = by[o] + sum_k g_H[t,b,k] * V[o,k]
// Tile 64b x 64o, 256 threads, thread = 4b x 4o, k-split f32x2 accumulators.
// Both operands k-contiguous in smem (no transpose); Vs XOR-swizzled.
// ---------------------------------------------------------------------------
__global__ void __launch_bounds__(256, 2)
rnn_logits_kernel(const float* __restrict__ Vm, const float* __restrict__ by,
                  float* __restrict__ out)
{
    __shared__ float As[64 * 32];    // [b][k], swizzled by ((b>>2)&7)
    __shared__ float Vs[64 * 32];    // [o][k], swizzled by ((o>>2)&7)

    const int t  = blockIdx.z;
    const int ob = blockIdx.x * 64;
    const int bb = blockIdx.y * 64;
    const int tid = threadIdx.x;
    const int tx = tid & 15;         // o rows 4tx .. 4tx+3
    const int ty = tid >> 4;         // b rows 4ty .. 4ty+3

    const float* A = g_H + (size_t)t * (B_ * H_) + (size_t)bb * H_;

    ull acc[4][4];
    #pragma unroll
    for (int m = 0; m < 4; ++m)
        #pragma unroll
        for (int n = 0; n < 4; ++n) acc[m][n] = 0ull;

    const int swA = ((ty & 1) << 4) | ((/*unused*/0));
    (void)swA;

    for (int kc = 0; kc < H_; kc += 32) {
        // Fill As: 64 rows x 32k = 512 float4, 2 per thread
        #pragma unroll
        for (int j = 0; j < 2; ++j) {
            int i  = tid + j * 256;
            int b  = i >> 3;
            int k4 = (i & 7) << 2;
            int o  = k4 ^ (((b >> 2) & 7) << 2);
            *(float4*)&As[b * 32 + o] =
                *(const float4*)&A[(size_t)b * H_ + kc + k4];
        }
        // Fill Vs: 64 rows x 32k
        #pragma unroll
        for (int j = 0; j < 2; ++j) {
            int i  = tid + j * 256;
            int o_ = i >> 3;
            int k4 = (i & 7) << 2;
            int o  = k4 ^ (((o_ >> 2) & 7) << 2);
            *(float4*)&Vs[o_ * 32 + o] =
                *(const float4*)&Vm[(size_t)(ob + o_) * H_ + kc + k4];
        }
        __syncthreads();

        const int sa = ((ty & 7) << 2);   // (4ty>>2)&7 == ty&7
        const int sv = ((tx & 7) << 2);
        #pragma unroll
        for (int k4 = 0; k4 < 32; k4 += 4) {
            ulonglong2 av[4], vv[4];
            #pragma unroll
            for (int m = 0; m < 4; ++m)
                av[m] = *(const ulonglong2*)&As[(4 * ty + m) * 32 + (k4 ^ sa)];
            #pragma unroll
            for (int n = 0; n < 4; ++n)
                vv[n] = *(const ulonglong2*)&Vs[(4 * tx + n) * 32 + (k4 ^ sv)];
            #pragma unroll
            for (int m = 0; m < 4; ++m)
                #pragma unroll
                for (int n = 0; n < 4; ++n) {
                    fma2(acc[m][n], av[m].x, vv[n].x);
                    fma2(acc[m][n], av[m].y, vv[n].y);
                }
        }
        __syncthreads();
    }

    const float4 byv = *(const float4*)&by[ob + 4 * tx];
    #pragma unroll
    for (int m = 0; m < 4; ++m) {
        float4 r = make_float4(pair_sum(acc[m][0]) + byv.x,
                               pair_sum(acc[m][1]) + byv.y,
                               pair_sum(acc[m][2]) + byv.z,
                               pair_sum(acc[m][3]) + byv.w);
        *(float4*)&out[((size_t)t * B_ + bb + 4 * ty + m) * O_ + ob + 4 * tx] = r;
    }
}

// Optional hT (H,B) appended after logits
__global__ void copy_hT_kernel(float* __restrict__ out) {
    int h = blockIdx.x;      // 512
    int b = threadIdx.x;     // 256
    out[(size_t)h * B_ + b] =
        g_H[(size_t)(T_ - 1) * (B_ * H_) + (size_t)b * H_ + h];
}

extern "C" void kernel_launch(void* const* d_in, const int* in_sizes, int n_in,
                              void* d_out, int out_size) {
    const int*   inp = (const int*)d_in[0];
    const float* h0  = (const float*)d_in[1];
    const float* U   = (const float*)d_in[2];
    const float* W   = (const float*)d_in[3];
    const float* Vm  = (const float*)d_in[4];
    const float* bh  = (const float*)d_in[5];
    const float* by  = (const float*)d_in[6];
    float* out = (float*)d_out;

    cudaFuncSetAttribute(rnn_recur_kernel,
                         cudaFuncAttributeMaxDynamicSharedMemorySize,
                         (int)(SMEM_A_WORDS * sizeof(float)));

    prep_h0t<<<B_, H_>>>(h0);

    rnn_recur_kernel<<<NBLK_A, 128, SMEM_A_WORDS * sizeof(float)>>>(inp, U, W, bh);

    dim3 gridB(O_ / 64, B_ / 64, T_);
    rnn_logits_kernel<<<gridB, 256>>>(Vm, by, out);

    if (out_size >= T_ * B_ * O_ + H_ * B_) {
        copy_hT_kernel<<<H_, B_>>>(out + (size_t)T_ * B_ * O_);
    }
}